// round 16
// baseline (speedup 1.0000x reference)
#include <cuda_runtime.h>
#include <cuda_fp16.h>
#include <cstdint>
#include <cfloat>

// Problem constants
#define BATCH 256
#define CW    8192
#define NC    64
#define NS    4096
#define NE    128
#define BM    128
#define BN    64
#define NCH   (NS / BN)      // 64 chunks
#define KS    8
#define NTH   512
#define EMBED_ELEMS (BATCH * CW)
#define XSPITCH 132
#define DELTA 0.5f

// ---- persistent scratch: pre-converted dict fragments + row norms ----
__device__ __align__(16) unsigned char g_bfrag[(size_t)NC * NCH * 16384]; // 64 MB
__device__ __align__(16) float g_dsq[NC * NS];                            // 1 MB

// ---- kernel B smem layout (bytes) ----
#define SM_BF    0            // 4 stages x 16384 (B fragment ring)
#define SM_DSQR  65536        // 4 stages x 256 (dsq ring)
#define SM_XS    66560        // [128][132] fp32 = 67584
#define SM_CANDS 134144       // [128][16] float = 8192
#define SM_CANDI 142336       // [128][16] int = 8192
#define SM_WIDXF 150528       // [128] int = 512
#define SM_TOTAL 151040

static __device__ __forceinline__ void mma_f16_f32(float4& c, uint32_t a0, uint32_t a1,
                                                   uint32_t a2, uint32_t a3,
                                                   uint32_t b0, uint32_t b1) {
    asm("mma.sync.aligned.m16n8k16.row.col.f32.f16.f16.f32 "
        "{%0,%1,%2,%3}, {%4,%5,%6,%7}, {%8,%9}, {%0,%1,%2,%3};"
        : "+f"(c.x), "+f"(c.y), "+f"(c.z), "+f"(c.w)
        : "r"(a0), "r"(a1), "r"(a2), "r"(a3), "r"(b0), "r"(b1));
}

static __device__ __forceinline__ uint32_t pack_h2(float f0, float f1) {
    __half2 h = __float22half2_rn(make_float2(f0, f1));
    return *(uint32_t*)&h;
}

static __device__ __forceinline__ void cpa16(uint32_t saddr, const void* g) {
    asm volatile("cp.async.cg.shared.global [%0], [%1], 16;" :: "r"(saddr), "l"(g));
}
#define CPA_COMMIT() asm volatile("cp.async.commit_group;" ::: "memory")
#define CPA_WAIT3()  asm volatile("cp.async.wait_group 3;" ::: "memory")

// ============ Kernel A: pre-convert dict -> fp16 fragment blobs + |d|^2 ============
// One block per (c, chunk). Blob layout identical to kernel B's BF stage:
//   offset(ksg, pair, unit=lane) = ksg*2048 + pair*512 + lane*16, uint4 =
//   { n8-frag halves from dict rows pair*16+g (hf0) and pair*16+8+g (hf1) }.
__global__ __launch_bounds__(512)
void vq_convert(const float* __restrict__ dict) {
    const int blk = blockIdx.x;            // c*64 + s
    const int tid = threadIdx.x;
    const float* drow0 = dict + (size_t)blk * 64 * NE;

    // fragment role: warp w handles slots 2w, 2w+1 (slot = ksg*4 + pair)
    const int w = tid >> 5, lane = tid & 31;
    const int g = lane >> 2, t = lane & 3;
    unsigned char* blob = g_bfrag + ((size_t)blk << 14);
    #pragma unroll
    for (int i = 0; i < 2; ++i) {
        const int slot = w * 2 + i;
        const int ksg = slot >> 2, pair = slot & 3;
        const int k0 = ksg * 16 + 2 * t;
        const float* r0 = drow0 + (size_t)(pair * 16 + g) * NE + k0;
        const float* r1 = r0 + 8 * NE;
        float2 a0 = *(const float2*)r0;
        float2 a1 = *(const float2*)(r0 + 8);
        float2 b0 = *(const float2*)r1;
        float2 b1 = *(const float2*)(r1 + 8);
        *(uint4*)(blob + slot * 512 + lane * 16) =
            make_uint4(pack_h2(a0.x, a0.y), pack_h2(a1.x, a1.y),
                       pack_h2(b0.x, b0.y), pack_h2(b1.x, b1.y));
    }

    // dsq role: 8 threads per row (L1-hot second read of the tile)
    {
        const int row = tid >> 3, seg = tid & 7;
        const float* rp = drow0 + (size_t)row * NE + seg * 16;
        float ss = 0.f;
        #pragma unroll
        for (int j = 0; j < 4; ++j) {
            float4 v = *(const float4*)(rp + j * 4);
            ss = fmaf(v.x, v.x, ss); ss = fmaf(v.y, v.y, ss);
            ss = fmaf(v.z, v.z, ss); ss = fmaf(v.w, v.w, ss);
        }
        ss += __shfl_xor_sync(0xffffffffu, ss, 1);
        ss += __shfl_xor_sync(0xffffffffu, ss, 2);
        ss += __shfl_xor_sync(0xffffffffu, ss, 4);
        if (seg == 0) g_dsq[blk * 64 + row] = ss;
    }
}

// ============ Kernel B: cp.async-fed approx GEMM -> top2 -> exact rescore ============
__global__ __launch_bounds__(NTH, 1)
void vq_fused(const float* __restrict__ x, const float* __restrict__ dict,
              float* __restrict__ out) {
    extern __shared__ char smem[];
    float* XS = (float*)(smem + SM_XS);
    float* cand_s = (float*)(smem + SM_CANDS);   // [128][16]
    int*   cand_i = (int*)(smem + SM_CANDI);     // [128][16]
    int*   widxf = (int*)(smem + SM_WIDXF);
    const uint32_t smem_u = (uint32_t)__cvta_generic_to_shared(smem);

    const int tid  = threadIdx.x;
    const int wid  = tid >> 5;
    const int lane = tid & 31;
    const int gid  = lane >> 2;
    const int tg   = lane & 3;
    const int mw   = wid & 7;          // 8 m-warps (16 rows each)
    const int nw   = wid >> 3;         // 2 n-warps (32 cols each)
    const int m0   = mw * 16;
    const int n0   = nw * 32;

    const int c  = blockIdx.x;
    const int b0 = blockIdx.y * BM;

// issue one chunk's B-blob (16 KB) + dsq (256 B) into ring stage (SN&3)
#define ISSUE_CHUNK(SN)                                                            \
    {                                                                              \
        const unsigned char* gsrc =                                                \
            g_bfrag + (((size_t)(c * NCH + (SN))) << 14) + tid * 32;               \
        const uint32_t sdst = smem_u + ((SN) & 3) * 16384 + tid * 32;              \
        cpa16(sdst, gsrc);                                                         \
        cpa16(sdst + 16, gsrc + 16);                                               \
        if (tid < 16)                                                              \
            cpa16(smem_u + SM_DSQR + ((SN) & 3) * 256 + tid * 16,                  \
                  g_dsq + c * NS + (SN) * 64 + tid * 4);                           \
        CPA_COMMIT();                                                              \
    }

    // ---- prologue: start the pipeline before anything else ----
    ISSUE_CHUNK(0)
    ISSUE_CHUNK(1)
    ISSUE_CHUNK(2)
    ISSUE_CHUNK(3)

    // ---- XS fill (coalesced fp32 x tile) ----
    {
        const int r = tid >> 2;
        const int q = tid & 3;
        const float* xr = x + (size_t)(b0 + r) * CW + (size_t)c * NE + q * 32;
        float* xsrow = XS + r * XSPITCH + q * 32;
        #pragma unroll
        for (int j = 0; j < 8; ++j)
            *(float4*)(xsrow + j * 4) = *(const float4*)(xr + j * 4);
    }
    __syncthreads();   // XS ready

    // ---- A-register build: x fragments live in registers for ALL chunks ----
    uint4 A[KS];
    {
        const int r0 = m0 + gid;
        #pragma unroll
        for (int ks = 0; ks < KS; ++ks) {
            const int kb = ks * 16 + 2 * tg;
            float2 f0 = *(const float2*)&XS[r0 * XSPITCH + kb];
            float2 f1 = *(const float2*)&XS[(r0 + 8) * XSPITCH + kb];
            float2 f2 = *(const float2*)&XS[r0 * XSPITCH + kb + 8];
            float2 f3 = *(const float2*)&XS[(r0 + 8) * XSPITCH + kb + 8];
            A[ks] = make_uint4(pack_h2(f0.x, f0.y), pack_h2(f1.x, f1.y),
                               pack_h2(f2.x, f2.y), pack_h2(f3.x, f3.y));
        }
    }

    // ---- per-thread state ----
    float4 acc[4];
    #pragma unroll
    for (int nt = 0; nt < 4; ++nt) acc[nt] = make_float4(0.f, 0.f, 0.f, 0.f);

    float b1[2], b2[2];
    uint32_t x12[2];                   // (x1 << 16) | x2
    #pragma unroll
    for (int i = 0; i < 2; ++i) { b1[i] = FLT_MAX; b2[i] = FLT_MAX; x12[i] = 0; }

    const int zr = tid >> 2;           // zero-fill row
    const int zj = tid & 3;
    const int cb = n0 + 2 * tg;

    for (int s = 0; s < NCH; ++s) {
        const int p = s & 3;

        CPA_WAIT3();                   // chunk s's group retired (groups in order)
        __syncthreads();               // stage data visible to all warps

        // ---- one-hot zero-fill: segment s, coalesced ----
        {
            float4* dst = (float4*)(out + (size_t)EMBED_ELEMS +
                                    ((size_t)(b0 + zr) * NC + c) * NS + (size_t)s * BN);
            #pragma unroll
            for (int j = 0; j < 4; ++j)
                __stwt(&dst[zj + 4 * j], make_float4(0.f, 0.f, 0.f, 0.f));
        }

        // ---- mma phase: 8 ks x (2 B LDS.128, A from registers, 4 HMMA) ----
        {
            const char* BFp = smem + p * 16384;
            #pragma unroll
            for (int ks = 0; ks < KS; ++ks) {
                uint4 B0 = *(const uint4*)(BFp + ks * 2048 + (nw * 2) * 512 + lane * 16);
                uint4 B1 = *(const uint4*)(BFp + ks * 2048 + (nw * 2 + 1) * 512 + lane * 16);
                mma_f16_f32(acc[0], A[ks].x, A[ks].y, A[ks].z, A[ks].w, B0.x, B0.y);
                mma_f16_f32(acc[1], A[ks].x, A[ks].y, A[ks].z, A[ks].w, B0.z, B0.w);
                mma_f16_f32(acc[2], A[ks].x, A[ks].y, A[ks].z, A[ks].w, B1.x, B1.y);
                mma_f16_f32(acc[3], A[ks].x, A[ks].y, A[ks].z, A[ks].w, B1.z, B1.w);
            }
        }

        // ---- epilogue: per row-slot min-of-8 + rare top-2 insert; reset accs ----
        {
            const float* dsqp = (const float*)(smem + SM_DSQR + p * 256);
            const float2 dv0 = *(const float2*)&dsqp[cb];
            const float2 dv1 = *(const float2*)&dsqp[cb + 8];
            const float2 dv2 = *(const float2*)&dsqp[cb + 16];
            const float2 dv3 = *(const float2*)&dsqp[cb + 24];
            const int base = s * BN + cb;
            #pragma unroll
            for (int h = 0; h < 2; ++h) {      // rows gid / gid+8
                float sa[8];
                sa[0] = fmaf(-2.f, h ? acc[0].z : acc[0].x, dv0.x);
                sa[1] = fmaf(-2.f, h ? acc[0].w : acc[0].y, dv0.y);
                sa[2] = fmaf(-2.f, h ? acc[1].z : acc[1].x, dv1.x);
                sa[3] = fmaf(-2.f, h ? acc[1].w : acc[1].y, dv1.y);
                sa[4] = fmaf(-2.f, h ? acc[2].z : acc[2].x, dv2.x);
                sa[5] = fmaf(-2.f, h ? acc[2].w : acc[2].y, dv2.y);
                sa[6] = fmaf(-2.f, h ? acc[3].z : acc[3].x, dv3.x);
                sa[7] = fmaf(-2.f, h ? acc[3].w : acc[3].y, dv3.y);
                const float m1 = fminf(fminf(fminf(sa[0], sa[1]), fminf(sa[2], sa[3])),
                                       fminf(fminf(sa[4], sa[5]), fminf(sa[6], sa[7])));
                if (m1 < b2[h]) {
                    int p1 = 0; float mv = sa[0];
                    #pragma unroll
                    for (int i = 1; i < 8; ++i)
                        if (sa[i] < mv) { mv = sa[i]; p1 = i; }
                    const uint32_t i1 = base + (p1 >> 1) * 8 + (p1 & 1);
                    if (mv < b1[h]) {
                        b2[h] = b1[h];
                        x12[h] = (i1 << 16) | (x12[h] >> 16);
                        b1[h] = mv;
                    } else {
                        b2[h] = mv;
                        x12[h] = (x12[h] & 0xFFFF0000u) | i1;
                    }
                    sa[p1] = FLT_MAX;
                    int p2 = 0; float mv2 = sa[0];
                    #pragma unroll
                    for (int i = 1; i < 8; ++i)
                        if (sa[i] < mv2) { mv2 = sa[i]; p2 = i; }
                    if (mv2 < b2[h]) {
                        b2[h] = mv2;
                        x12[h] = (x12[h] & 0xFFFF0000u) |
                                 (uint32_t)(base + (p2 >> 1) * 8 + (p2 & 1));
                    }
                }
            }
            #pragma unroll
            for (int nt = 0; nt < 4; ++nt) acc[nt] = make_float4(0.f, 0.f, 0.f, 0.f);
        }
        __syncthreads();   // all reads of stage p done before refill

        // ---- refill stage p with chunk s+4 (dummy commit keeps group count uniform) ----
        if (s + 4 < NCH) { ISSUE_CHUNK(s + 4) }
        else             { CPA_COMMIT(); }
    }

    // ---- stage 1: dump candidates (16 per row) ----
    {
        const int slotid = nw * 4 + tg;        // 0..7
        #pragma unroll
        for (int h = 0; h < 2; ++h) {
            const int R = m0 + gid + h * 8;
            cand_s[R * 16 + slotid * 2]     = b1[h];
            cand_s[R * 16 + slotid * 2 + 1] = b2[h];
            cand_i[R * 16 + slotid * 2]     = (int)(x12[h] >> 16);
            cand_i[R * 16 + slotid * 2 + 1] = (int)(x12[h] & 0xFFFFu);
        }
    }
    __syncthreads();

    // ---- stage 2: warp-per-row exact rescore of near-min candidates ----
    const float* dictc = dict + (size_t)c * NS * NE;
    for (int rr = 0; rr < 8; ++rr) {
        const int r = wid * 8 + rr;
        float sc = (lane < 16) ? cand_s[r * 16 + lane] : FLT_MAX;
        int   ix = (lane < 16) ? cand_i[r * 16 + lane] : 0;
        float m = sc;
        #pragma unroll
        for (int off = 16; off; off >>= 1)
            m = fminf(m, __shfl_xor_sync(0xffffffffu, m, off));
        float es = FLT_MAX;
        if (lane < 16 && sc <= m + DELTA) {
            const float4* dp = (const float4*)(dictc + (size_t)ix * NE);
            const float4* xp = (const float4*)(XS + r * XSPITCH);
            float dot = 0.f, ds2 = 0.f;
            #pragma unroll 8
            for (int j = 0; j < 32; ++j) {
                const float4 d4 = __ldg(&dp[j]);
                const float4 x4 = xp[j];
                dot = fmaf(d4.x, x4.x, dot); ds2 = fmaf(d4.x, d4.x, ds2);
                dot = fmaf(d4.y, x4.y, dot); ds2 = fmaf(d4.y, d4.y, ds2);
                dot = fmaf(d4.z, x4.z, dot); ds2 = fmaf(d4.z, d4.z, ds2);
                dot = fmaf(d4.w, x4.w, dot); ds2 = fmaf(d4.w, d4.w, ds2);
            }
            es = fmaf(-2.f, dot, ds2);
        }
        #pragma unroll
        for (int off = 16; off; off >>= 1) {
            const float oe = __shfl_xor_sync(0xffffffffu, es, off);
            const int   oi = __shfl_xor_sync(0xffffffffu, ix, off);
            if (oe < es || (oe == es && oi < ix)) { es = oe; ix = oi; }
        }
        if (lane == 0) {
            out[(size_t)EMBED_ELEMS + ((size_t)(b0 + r) * NC + c) * NS + ix] = 1.0f;
            widxf[r] = ix;
        }
    }
    __syncthreads();

    // ---- stage 3: gather nearest codewords into the embed region ----
    {
        const int r = tid >> 2;
        const int q = tid & 3;
        const int ix = widxf[r];
        const float4* src = (const float4*)(dictc + (size_t)ix * NE) + q * 8;
        float4* dst = (float4*)(out + (size_t)(b0 + r) * CW + c * NE) + q * 8;
        #pragma unroll
        for (int j = 0; j < 8; ++j) __stwt(&dst[j], src[j]);
    }
}

extern "C" void kernel_launch(void* const* d_in, const int* in_sizes, int n_in,
                              void* d_out, int out_size) {
    const float* x    = (const float*)d_in[0];   // [256, 8192]
    const float* dict = (const float*)d_in[1];   // [64, 4096, 128]
    float* out = (float*)d_out;

    cudaFuncSetAttribute(vq_fused,
                         cudaFuncAttributeMaxDynamicSharedMemorySize, SM_TOTAL);

    vq_convert<<<NC * NCH, 512>>>(dict);
    vq_fused<<<dim3(NC, BATCH / BM), NTH, SM_TOTAL>>>(x, dict, out);
}

// round 17
// speedup vs baseline: 1.3654x; 1.3654x over previous
#include <cuda_runtime.h>
#include <cuda_fp16.h>
#include <cstdint>
#include <cfloat>

// Problem constants
#define BATCH 256
#define CW    8192
#define NC    64
#define NS    4096
#define NE    128
#define BM    64             // batch rows per CTA (4 b-tiles, 2 CTAs/SM)
#define BN    64
#define NCH   (NS / BN)      // 64 chunks
#define KS    8
#define NTH   512
#define EMBED_ELEMS (BATCH * CW)
#define XSPITCH 132
#define DELTA 0.5f

// ---- persistent scratch: pre-converted dict fragments + row norms ----
__device__ __align__(16) unsigned char g_bfrag[(size_t)NC * NCH * 16384]; // 64 MB
__device__ __align__(16) float g_dsq[NC * NS];                            // 1 MB

// ---- kernel B smem layout (bytes): 100352 total -> 2 CTAs/SM ----
#define SM_BF    0            // 3 stages x 16384 (B fragment ring)
#define SM_DSQR  49152        // 3 stages x 256
#define SM_XS    49920        // [64][132] fp32 = 33792
#define SM_CANDS 83712        // [64][32] float = 8192
#define SM_CANDI 91904        // [64][32] int = 8192
#define SM_WIDXF 100096       // [64] int = 256
#define SM_TOTAL 100352

static __device__ __forceinline__ void mma_f16_f32(float4& c, uint32_t a0, uint32_t a1,
                                                   uint32_t a2, uint32_t a3,
                                                   uint32_t b0, uint32_t b1) {
    asm("mma.sync.aligned.m16n8k16.row.col.f32.f16.f16.f32 "
        "{%0,%1,%2,%3}, {%4,%5,%6,%7}, {%8,%9}, {%0,%1,%2,%3};"
        : "+f"(c.x), "+f"(c.y), "+f"(c.z), "+f"(c.w)
        : "r"(a0), "r"(a1), "r"(a2), "r"(a3), "r"(b0), "r"(b1));
}

static __device__ __forceinline__ uint32_t pack_h2(float f0, float f1) {
    __half2 h = __float22half2_rn(make_float2(f0, f1));
    return *(uint32_t*)&h;
}

static __device__ __forceinline__ void cpa16(uint32_t saddr, const void* g) {
    asm volatile("cp.async.cg.shared.global [%0], [%1], 16;" :: "r"(saddr), "l"(g));
}
#define CPA_COMMIT() asm volatile("cp.async.commit_group;" ::: "memory")
#define CPA_WAIT2()  asm volatile("cp.async.wait_group 2;" ::: "memory")

// ============ Kernel A: pre-convert dict -> fp16 fragment blobs + |d|^2 ============
__global__ __launch_bounds__(512)
void vq_convert(const float* __restrict__ dict) {
    const int blk = blockIdx.x;            // c*64 + s
    const int tid = threadIdx.x;
    const float* drow0 = dict + (size_t)blk * 64 * NE;

    const int w = tid >> 5, lane = tid & 31;
    const int g = lane >> 2, t = lane & 3;
    unsigned char* blob = g_bfrag + ((size_t)blk << 14);
    #pragma unroll
    for (int i = 0; i < 2; ++i) {
        const int slot = w * 2 + i;            // slot = ksg*4 + pair
        const int ksg = slot >> 2, pair = slot & 3;
        const int k0 = ksg * 16 + 2 * t;
        const float* r0 = drow0 + (size_t)(pair * 16 + g) * NE + k0;
        const float* r1 = r0 + 8 * NE;
        float2 a0 = *(const float2*)r0;
        float2 a1 = *(const float2*)(r0 + 8);
        float2 b0 = *(const float2*)r1;
        float2 b1 = *(const float2*)(r1 + 8);
        *(uint4*)(blob + slot * 512 + lane * 16) =
            make_uint4(pack_h2(a0.x, a0.y), pack_h2(a1.x, a1.y),
                       pack_h2(b0.x, b0.y), pack_h2(b1.x, b1.y));
    }

    {
        const int row = tid >> 3, seg = tid & 7;
        const float* rp = drow0 + (size_t)row * NE + seg * 16;
        float ss = 0.f;
        #pragma unroll
        for (int j = 0; j < 4; ++j) {
            float4 v = *(const float4*)(rp + j * 4);
            ss = fmaf(v.x, v.x, ss); ss = fmaf(v.y, v.y, ss);
            ss = fmaf(v.z, v.z, ss); ss = fmaf(v.w, v.w, ss);
        }
        ss += __shfl_xor_sync(0xffffffffu, ss, 1);
        ss += __shfl_xor_sync(0xffffffffu, ss, 2);
        ss += __shfl_xor_sync(0xffffffffu, ss, 4);
        if (seg == 0) g_dsq[blk * 64 + row] = ss;
    }
}

// ============ Kernel B: 2 CTAs/SM, cp.async-fed GEMM -> top2 -> exact rescore ============
__global__ __launch_bounds__(NTH, 2)
void vq_fused(const float* __restrict__ x, const float* __restrict__ dict,
              float* __restrict__ out) {
    extern __shared__ char smem[];
    float* XS = (float*)(smem + SM_XS);
    float* cand_s = (float*)(smem + SM_CANDS);   // [64][32]
    int*   cand_i = (int*)(smem + SM_CANDI);     // [64][32]
    int*   widxf = (int*)(smem + SM_WIDXF);
    const uint32_t smem_u = (uint32_t)__cvta_generic_to_shared(smem);

    const int tid  = threadIdx.x;
    const int wid  = tid >> 5;
    const int lane = tid & 31;
    const int gid  = lane >> 2;
    const int tg   = lane & 3;
    const int mw   = wid & 3;          // 4 m-warps (16 rows each)
    const int nw   = wid >> 2;         // 4 n-warps (16 cols each)
    const int m0   = mw * 16;
    const int n0   = nw * 16;

    const int c  = blockIdx.x;
    const int b0 = blockIdx.y * BM;

// issue one chunk's blob (16 KB) + dsq (256 B) into ring stage (SN % 3)
#define ISSUE_CHUNK(SN)                                                            \
    {                                                                              \
        const int stg_ = (SN) % 3;                                                 \
        const unsigned char* gsrc =                                                \
            g_bfrag + (((size_t)(c * NCH + (SN))) << 14) + tid * 32;               \
        const uint32_t sdst = smem_u + stg_ * 16384 + tid * 32;                    \
        cpa16(sdst, gsrc);                                                         \
        cpa16(sdst + 16, gsrc + 16);                                               \
        if (tid < 16)                                                              \
            cpa16(smem_u + SM_DSQR + stg_ * 256 + tid * 16,                        \
                  g_dsq + c * NS + (SN) * 64 + tid * 4);                           \
        CPA_COMMIT();                                                              \
    }

    // ---- prologue: fill the 3-stage pipeline ----
    ISSUE_CHUNK(0)
    ISSUE_CHUNK(1)
    ISSUE_CHUNK(2)

    // ---- XS fill (coalesced fp32 x tile, 64 rows) ----
    {
        const int r = tid >> 3;
        const int seg = tid & 7;
        const float* xr = x + (size_t)(b0 + r) * CW + (size_t)c * NE + seg * 16;
        float* xsrow = XS + r * XSPITCH + seg * 16;
        #pragma unroll
        for (int j = 0; j < 4; ++j)
            *(float4*)(xsrow + j * 4) = *(const float4*)(xr + j * 4);
    }
    __syncthreads();   // XS ready

    // ---- A-register build: x fragments live in registers for ALL chunks ----
    uint4 A[KS];
    {
        const int r0 = m0 + gid;
        #pragma unroll
        for (int ks = 0; ks < KS; ++ks) {
            const int kb = ks * 16 + 2 * tg;
            float2 f0 = *(const float2*)&XS[r0 * XSPITCH + kb];
            float2 f1 = *(const float2*)&XS[(r0 + 8) * XSPITCH + kb];
            float2 f2 = *(const float2*)&XS[r0 * XSPITCH + kb + 8];
            float2 f3 = *(const float2*)&XS[(r0 + 8) * XSPITCH + kb + 8];
            A[ks] = make_uint4(pack_h2(f0.x, f0.y), pack_h2(f1.x, f1.y),
                               pack_h2(f2.x, f2.y), pack_h2(f3.x, f3.y));
        }
    }

    // ---- per-thread state ----
    float4 acc[2];
    acc[0] = make_float4(0.f, 0.f, 0.f, 0.f);
    acc[1] = make_float4(0.f, 0.f, 0.f, 0.f);

    float b1[2], b2[2];
    uint32_t x12[2];
    #pragma unroll
    for (int i = 0; i < 2; ++i) { b1[i] = FLT_MAX; b2[i] = FLT_MAX; x12[i] = 0; }

    const int zr = tid >> 3;           // zero-fill row (0..63)
    const int zj = tid & 7;            // float4 slot
    const int cb = n0 + 2 * tg;

    for (int s = 0; s < NCH; ++s) {
        const int p = s % 3;

        CPA_WAIT2();                   // chunk s's group retired
        __syncthreads();               // stage visible to all warps

        // ---- one-hot zero-fill: segment s of 64 owned rows ----
        {
            float4* dst = (float4*)(out + (size_t)EMBED_ELEMS +
                                    ((size_t)(b0 + zr) * NC + c) * NS + (size_t)s * BN);
            __stwt(&dst[zj], make_float4(0.f, 0.f, 0.f, 0.f));
            __stwt(&dst[zj + 8], make_float4(0.f, 0.f, 0.f, 0.f));
        }

        // ---- mma phase: 8 ks x (1 B LDS.128, A from registers, 2 HMMA) ----
        {
            const char* BFp = smem + p * 16384;
            #pragma unroll
            for (int ks = 0; ks < KS; ++ks) {
                uint4 Bv = *(const uint4*)(BFp + ks * 2048 + nw * 512 + lane * 16);
                mma_f16_f32(acc[0], A[ks].x, A[ks].y, A[ks].z, A[ks].w, Bv.x, Bv.y);
                mma_f16_f32(acc[1], A[ks].x, A[ks].y, A[ks].z, A[ks].w, Bv.z, Bv.w);
            }
        }

        // ---- epilogue: min-of-4 + rare top-2 insert per row-slot; reset accs ----
        {
            const float* dsqp = (const float*)(smem + SM_DSQR + p * 256);
            const float2 dv0 = *(const float2*)&dsqp[cb];
            const float2 dv1 = *(const float2*)&dsqp[cb + 8];
            const int base = s * BN + cb;
            #pragma unroll
            for (int h = 0; h < 2; ++h) {      // rows gid / gid+8
                const float s0 = fmaf(-2.f, h ? acc[0].z : acc[0].x, dv0.x);
                const float s1 = fmaf(-2.f, h ? acc[0].w : acc[0].y, dv0.y);
                const float s2 = fmaf(-2.f, h ? acc[1].z : acc[1].x, dv1.x);
                const float s3 = fmaf(-2.f, h ? acc[1].w : acc[1].y, dv1.y);
                const float m1 = fminf(fminf(s0, s1), fminf(s2, s3));
                if (m1 < b2[h]) {
                    const float mn01 = fminf(s0, s1), mx01 = fmaxf(s0, s1);
                    const float mn23 = fminf(s2, s3), mx23 = fmaxf(s2, s3);
                    const float m2 = fminf(fminf(mx01, mx23), fmaxf(mn01, mn23));
                    const int p1 = (m1 == s0) ? 0 : (m1 == s1) ? 1 : (m1 == s2) ? 2 : 3;
                    const uint32_t i1 = base + (p1 & 1) + (p1 >> 1) * 8;
                    if (m1 < b1[h]) {
                        b2[h] = b1[h];
                        x12[h] = (i1 << 16) | (x12[h] >> 16);
                        b1[h] = m1;
                    } else {
                        b2[h] = m1;
                        x12[h] = (x12[h] & 0xFFFF0000u) | i1;
                    }
                    if (m2 < b2[h]) {
                        int p2;
                        if (m2 == s0 && p1 != 0) p2 = 0;
                        else if (m2 == s1 && p1 != 1) p2 = 1;
                        else if (m2 == s2 && p1 != 2) p2 = 2;
                        else p2 = 3;
                        b2[h] = m2;
                        x12[h] = (x12[h] & 0xFFFF0000u) |
                                 (uint32_t)(base + (p2 & 1) + (p2 >> 1) * 8);
                    }
                }
            }
            acc[0] = make_float4(0.f, 0.f, 0.f, 0.f);
            acc[1] = make_float4(0.f, 0.f, 0.f, 0.f);
        }
        __syncthreads();   // all reads of stage p done before refill

        // ---- refill stage p with chunk s+3 (dummy commit keeps group count uniform) ----
        if (s + 3 < NCH) { ISSUE_CHUNK(s + 3) }
        else             { CPA_COMMIT(); }
    }

    // ---- stage 1: dump candidates (32 per row) ----
    {
        const int slotid = nw * 4 + tg;        // 0..15
        #pragma unroll
        for (int h = 0; h < 2; ++h) {
            const int R = m0 + gid + h * 8;
            cand_s[R * 32 + slotid * 2]     = b1[h];
            cand_s[R * 32 + slotid * 2 + 1] = b2[h];
            cand_i[R * 32 + slotid * 2]     = (int)(x12[h] >> 16);
            cand_i[R * 32 + slotid * 2 + 1] = (int)(x12[h] & 0xFFFFu);
        }
    }
    __syncthreads();

    // ---- stage 2: warp-per-row exact rescore (4 rows per warp) ----
    const float* dictc = dict + (size_t)c * NS * NE;
    for (int rr = 0; rr < 4; ++rr) {
        const int r = wid * 4 + rr;
        float sc = cand_s[r * 32 + lane];
        int   ix = cand_i[r * 32 + lane];
        float m = sc;
        #pragma unroll
        for (int off = 16; off; off >>= 1)
            m = fminf(m, __shfl_xor_sync(0xffffffffu, m, off));
        float es = FLT_MAX;
        if (sc <= m + DELTA) {
            const float4* dp = (const float4*)(dictc + (size_t)ix * NE);
            const float4* xp = (const float4*)(XS + r * XSPITCH);
            float dot = 0.f, ds2 = 0.f;
            #pragma unroll 8
            for (int j = 0; j < 32; ++j) {
                const float4 d4 = __ldg(&dp[j]);
                const float4 x4 = xp[j];
                dot = fmaf(d4.x, x4.x, dot); ds2 = fmaf(d4.x, d4.x, ds2);
                dot = fmaf(d4.y, x4.y, dot); ds2 = fmaf(d4.y, d4.y, ds2);
                dot = fmaf(d4.z, x4.z, dot); ds2 = fmaf(d4.z, d4.z, ds2);
                dot = fmaf(d4.w, x4.w, dot); ds2 = fmaf(d4.w, d4.w, ds2);
            }
            es = fmaf(-2.f, dot, ds2);
        }
        #pragma unroll
        for (int off = 16; off; off >>= 1) {
            const float oe = __shfl_xor_sync(0xffffffffu, es, off);
            const int   oi = __shfl_xor_sync(0xffffffffu, ix, off);
            if (oe < es || (oe == es && oi < ix)) { es = oe; ix = oi; }
        }
        if (lane == 0) {
            out[(size_t)EMBED_ELEMS + ((size_t)(b0 + r) * NC + c) * NS + ix] = 1.0f;
            widxf[r] = ix;
        }
    }
    __syncthreads();

    // ---- stage 3: gather nearest codewords (8 threads / row) ----
    {
        const int r = tid >> 3;
        const int q = tid & 7;
        const int ix = widxf[r];
        const float4* src = (const float4*)(dictc + (size_t)ix * NE) + q * 4;
        float4* dst = (float4*)(out + (size_t)(b0 + r) * CW + c * NE) + q * 4;
        #pragma unroll
        for (int j = 0; j < 4; ++j) __stwt(&dst[j], src[j]);
    }
}

extern "C" void kernel_launch(void* const* d_in, const int* in_sizes, int n_in,
                              void* d_out, int out_size) {
    const float* x    = (const float*)d_in[0];   // [256, 8192]
    const float* dict = (const float*)d_in[1];   // [64, 4096, 128]
    float* out = (float*)d_out;

    cudaFuncSetAttribute(vq_fused,
                         cudaFuncAttributeMaxDynamicSharedMemorySize, SM_TOTAL);

    vq_convert<<<NC * NCH, 512>>>(dict);
    vq_fused<<<dim3(NC, BATCH / BM), NTH, SM_TOTAL>>>(x, dict, out);
}